// round 2
// baseline (speedup 1.0000x reference)
#include <cuda_runtime.h>
#include <math.h>

// Problem dims (fixed by the dataset)
#define B_DIM 4
#define S_DIM 4096
#define D_IN  1024
#define N_ST  1024
#define M_DIM (B_DIM * S_DIM)   // 16384
#define K_DIM 1024

// ---------------- scratch (static device arrays; no cudaMalloc allowed) -----
__device__ float g_xp[(size_t)M_DIM * N_ST];  // x @ W_in^T + b_in  (raw)
__device__ float g_r [(size_t)M_DIM * N_ST];  // x @ W_r^T  + b_r   (raw, pre-sigmoid)
__device__ float g_i [(size_t)M_DIM * N_ST];  // x @ W_i^T  + b_i   (raw, pre-sigmoid)
__device__ float g_hs[(size_t)M_DIM * N_ST];  // scan outputs h_t

// ---------------- SGEMM-TN: C[m,n] = sum_k A[m,k]*Bw[n,k] + bias[n] ---------
// A: M x K row-major (K contiguous), Bw: N x K row-major (K contiguous).
// Tiles: 128x128x16, 256 threads, 8x8 micro-tile per thread.
// Inner loop uses fma.rn.f32x2 (Blackwell packed fp32 FMA, 2 FMA lanes/instr)
// with the A tile stored DUPLICATED in smem so the (a,a) pair is a plain
// 64-bit load — no per-iteration packing movs.

constexpr int BM = 128, BN = 128, BK = 16;
constexpr int GEMM_THREADS = 256;
constexpr int LDA2 = 2 * BM + 12;   // duplicated-A row stride in floats (268)
constexpr int LDB  = BN + 4;        // B row stride in floats (132)
constexpr int SMEM_BYTES = (2 * BK * LDA2 + 2 * BK * LDB) * 4;  // 51200 B

__global__ __launch_bounds__(GEMM_THREADS, 2)
void sgemm_tn(const float* __restrict__ A,
              const float* __restrict__ Bw,
              const float* __restrict__ bias,
              float* __restrict__ C)
{
    extern __shared__ float smem[];
    float (*As)[BK][LDA2] = (float (*)[BK][LDA2])smem;               // [2][BK][LDA2]
    float (*Bs)[BK][LDB]  = (float (*)[BK][LDB])(smem + 2 * BK * LDA2);

    const int tid = threadIdx.x;
    const int tx  = tid & 15;    // 0..15 -> col group (8 cols each)
    const int ty  = tid >> 4;    // 0..15 -> row group (8 rows each)
    const int mBase = blockIdx.y * BM;
    const int nBase = blockIdx.x * BN;

    // global-load mapping: each thread loads 2 float4 per matrix per tile
    const int lrow = tid >> 2;          // 0..63
    const int lk4  = (tid & 3) * 4;     // 0,4,8,12

    const float* Aptr = A  + (size_t)(mBase + lrow) * K_DIM + lk4;
    const float* Bptr = Bw + (size_t)(nBase + lrow) * K_DIM + lk4;

    float4 ra[2], rb[2];

    auto loadTile = [&](int k0) {
        ra[0] = *(const float4*)(Aptr + k0);
        ra[1] = *(const float4*)(Aptr + (size_t)64 * K_DIM + k0);
        rb[0] = *(const float4*)(Bptr + k0);
        rb[1] = *(const float4*)(Bptr + (size_t)64 * K_DIM + k0);
    };
    auto storeTile = [&](int buf) {
        #pragma unroll
        for (int it = 0; it < 2; ++it) {
            const int row = lrow + it * 64;
            const float va[4] = {ra[it].x, ra[it].y, ra[it].z, ra[it].w};
            const float vb[4] = {rb[it].x, rb[it].y, rb[it].z, rb[it].w};
            #pragma unroll
            for (int j = 0; j < 4; ++j) {
                As[buf][lk4 + j][2 * row]     = va[j];   // duplicated pair (a,a)
                As[buf][lk4 + j][2 * row + 1] = va[j];
                Bs[buf][lk4 + j][row]         = vb[j];
            }
        }
    };

    unsigned long long acc[8][4];        // 8 rows x 4 col-pairs, packed f32x2
    #pragma unroll
    for (int i = 0; i < 8; ++i)
        #pragma unroll
        for (int j = 0; j < 4; ++j) acc[i][j] = 0ull;

    loadTile(0);
    storeTile(0);
    __syncthreads();

    int buf = 0;
    constexpr int NT = K_DIM / BK;       // 64
    #pragma unroll 1
    for (int kt = 0; kt < NT; ++kt) {
        if (kt + 1 < NT) loadTile((kt + 1) * BK);
        #pragma unroll
        for (int kk = 0; kk < BK; ++kk) {
            unsigned long long ap[8], bp[4];
            const ulonglong2* a2 = (const ulonglong2*)&As[buf][kk][ty * 16];
            ulonglong2 t0 = a2[0], t1 = a2[1], t2 = a2[2], t3 = a2[3];
            ap[0] = t0.x; ap[1] = t0.y; ap[2] = t1.x; ap[3] = t1.y;
            ap[4] = t2.x; ap[5] = t2.y; ap[6] = t3.x; ap[7] = t3.y;
            const ulonglong2* b2 = (const ulonglong2*)&Bs[buf][kk][tx * 8];
            ulonglong2 u0 = b2[0], u1 = b2[1];
            bp[0] = u0.x; bp[1] = u0.y; bp[2] = u1.x; bp[3] = u1.y;
            #pragma unroll
            for (int i = 0; i < 8; ++i)
                #pragma unroll
                for (int j = 0; j < 4; ++j)
                    asm("fma.rn.f32x2 %0, %1, %2, %0;"
                        : "+l"(acc[i][j]) : "l"(ap[i]), "l"(bp[j]));
        }
        if (kt + 1 < NT) {
            storeTile(buf ^ 1);
            buf ^= 1;
            __syncthreads();
        }
    }

    // epilogue: unpack + bias + store
    const int row0 = mBase + ty * 8;
    const int col0 = nBase + tx * 8;
    float bv[8];
    #pragma unroll
    for (int j = 0; j < 8; ++j) bv[j] = bias[col0 + j];

    #pragma unroll
    for (int i = 0; i < 8; ++i) {
        float o[8];
        #pragma unroll
        for (int j = 0; j < 4; ++j) {
            o[2 * j]     = __uint_as_float((unsigned)(acc[i][j] & 0xffffffffull)) + bv[2 * j];
            o[2 * j + 1] = __uint_as_float((unsigned)(acc[i][j] >> 32))           + bv[2 * j + 1];
        }
        float* cp = C + (size_t)(row0 + i) * N_ST + col0;
        *(float4*)(cp)     = make_float4(o[0], o[1], o[2], o[3]);
        *(float4*)(cp + 4) = make_float4(o[4], o[5], o[6], o[7]);
    }
}

// ---------------- fused gate + sequential scan ------------------------------
// One thread per (b, n) chain. Reads raw projections, computes
//   r = sigmoid(xr), i = sigmoid(xi), a = sigmoid(-8*softplus(log_decay)*r),
//   u = sqrt(1 - a^2 + 1e-6) * i * xp,  h = a*h + u
// and writes hs (and h_last into the tail of d_out if there is room).
// MUFU-based sigmoid: decay is strong (a ~ 0.05 at log_decay=0), so the
// recurrence does not accumulate the ~2^-22 MUFU error.

__device__ __forceinline__ float sigmoidf_(float x) {
    return 1.0f / (1.0f + __expf(-x));
}

__global__ void scan_kernel(const float* __restrict__ h0,
                            const float* __restrict__ log_decay,
                            float* __restrict__ hlast_out)
{
    const int gid = blockIdx.x * blockDim.x + threadIdx.x;   // 0..4095
    const int b = gid >> 10;
    const int n = gid & 1023;

    const float ld = log_decay[n];
    const float sp = (ld > 20.0f) ? ld : log1pf(__expf(ld));   // softplus
    const float c  = -8.0f * sp;

    float h = h0[gid];

    const size_t base = (size_t)b * S_DIM * N_ST + n;
    const float* xp = g_xp + base;
    const float* xr = g_r  + base;
    const float* xi = g_i  + base;
    float*       hs = g_hs + base;

    #pragma unroll 4
    for (int s = 0; s < S_DIM; ++s) {
        const size_t off = (size_t)s * N_ST;
        const float rv = sigmoidf_(xr[off]);
        const float iv = sigmoidf_(xi[off]);
        const float a  = sigmoidf_(c * rv);
        const float scale = sqrtf((1.0f - a * a) + 1e-6f);
        const float u = scale * iv * xp[off];
        h = a * h + u;
        hs[off] = h;
    }
    if (hlast_out) hlast_out[gid] = h;
}

// ---------------- launcher --------------------------------------------------
extern "C" void kernel_launch(void* const* d_in, const int* in_sizes, int n_in,
                              void* d_out, int out_size)
{
    const float* x         = (const float*)d_in[0];
    const float* h0        = (const float*)d_in[1];
    const float* W_in      = (const float*)d_in[2];
    const float* b_in      = (const float*)d_in[3];
    const float* W_r       = (const float*)d_in[4];
    const float* b_r       = (const float*)d_in[5];
    const float* W_i       = (const float*)d_in[6];
    const float* b_i       = (const float*)d_in[7];
    const float* log_decay = (const float*)d_in[8];
    const float* W_out     = (const float*)d_in[9];
    const float* b_out     = (const float*)d_in[10];
    float* out = (float*)d_out;

    void *p_xp, *p_r, *p_i, *p_hs;
    cudaGetSymbolAddress(&p_xp, g_xp);
    cudaGetSymbolAddress(&p_r,  g_r);
    cudaGetSymbolAddress(&p_i,  g_i);
    cudaGetSymbolAddress(&p_hs, g_hs);

    cudaFuncSetAttribute(sgemm_tn, cudaFuncAttributeMaxDynamicSharedMemorySize,
                         SMEM_BYTES);

    dim3 grid(N_ST / BN, M_DIM / BM);   // (8, 128); x-fast -> A tile reuse in L2

    // three input projections (raw + bias; nonlinearity fused into the scan)
    sgemm_tn<<<grid, GEMM_THREADS, SMEM_BYTES>>>(x, W_in, b_in, (float*)p_xp);
    sgemm_tn<<<grid, GEMM_THREADS, SMEM_BYTES>>>(x, W_r,  b_r,  (float*)p_r);
    sgemm_tn<<<grid, GEMM_THREADS, SMEM_BYTES>>>(x, W_i,  b_i,  (float*)p_i);

    // sequential scan over time; writes hs and (if present) h_last
    const long long need = (long long)M_DIM * D_IN + (long long)B_DIM * N_ST;
    float* hlast = ((long long)out_size >= need) ? out + (size_t)M_DIM * D_IN
                                                 : nullptr;
    scan_kernel<<<128, 32>>>(h0, log_decay, hlast);

    // output projection: out[m,d] = sum_n hs[m,n] * W_out[d,n] + b_out[d]
    sgemm_tn<<<grid, GEMM_THREADS, SMEM_BYTES>>>((float*)p_hs, W_out, b_out, out);
}

// round 4
// speedup vs baseline: 5.4067x; 5.4067x over previous
#include <cuda_runtime.h>
#include <cuda_bf16.h>
#include <math.h>
#include <stdint.h>

// ---------------- problem dims ----------------------------------------------
#define B_DIM 4
#define S_DIM 4096
#define D_IN  1024
#define N_ST  1024
#define M_DIM (B_DIM * S_DIM)      // 16384
#define K_DIM 1024

// ---------------- static scratch (8-byte aligned via ull storage) -----------
__device__ float              g_xp  [(size_t)M_DIM * N_ST];  // x@W_in^T + b_in
__device__ float              g_r   [(size_t)M_DIM * N_ST];  // pre-sigmoid r
__device__ float              g_i   [(size_t)M_DIM * N_ST];  // pre-sigmoid i
__device__ unsigned long long g_xhi [(size_t)M_DIM * K_DIM / 4];  // bf16 hi of x
__device__ unsigned long long g_xlo [(size_t)M_DIM * K_DIM / 4];  // bf16 lo of x
__device__ unsigned long long g_hshi[(size_t)M_DIM * N_ST / 4];   // bf16 hi of hs
__device__ unsigned long long g_hslo[(size_t)M_DIM * N_ST / 4];   // bf16 lo of hs
__device__ unsigned long long g_whi [4 * 1024 * 1024 / 4];        // 4 weights hi
__device__ unsigned long long g_wlo [4 * 1024 * 1024 / 4];        // 4 weights lo

// ---------------- helpers ----------------------------------------------------
__device__ __forceinline__ uint32_t s2u(const void* p) {
    uint32_t a;
    asm("{ .reg .u64 t; cvta.to.shared.u64 t, %1; cvt.u32.u64 %0, t; }"
        : "=r"(a) : "l"(p));
    return a;
}
__device__ __forceinline__ void ldsm4(uint32_t* r, uint32_t a) {
    asm volatile("ldmatrix.sync.aligned.m8n8.x4.shared.b16 {%0,%1,%2,%3},[%4];"
                 : "=r"(r[0]), "=r"(r[1]), "=r"(r[2]), "=r"(r[3]) : "r"(a));
}
__device__ __forceinline__ void mma_bf16(float* d, const uint32_t* a,
                                         uint32_t b0, uint32_t b1) {
    asm volatile("mma.sync.aligned.m16n8k16.row.col.f32.bf16.bf16.f32 "
                 "{%0,%1,%2,%3},{%4,%5,%6,%7},{%8,%9},{%0,%1,%2,%3};"
                 : "+f"(d[0]), "+f"(d[1]), "+f"(d[2]), "+f"(d[3])
                 : "r"(a[0]), "r"(a[1]), "r"(a[2]), "r"(a[3]), "r"(b0), "r"(b1));
}
__device__ __forceinline__ void cpasync16(uint32_t s, const void* g) {
    asm volatile("cp.async.cg.shared.global [%0],[%1],16;" :: "r"(s), "l"(g));
}

// ---------------- bf16 hi/lo split ------------------------------------------
__global__ void split_bf16(const float4* __restrict__ in,
                           unsigned long long* __restrict__ hi,
                           unsigned long long* __restrict__ lo, int n4) {
    int i = blockIdx.x * blockDim.x + threadIdx.x;
    if (i >= n4) return;
    float4 v = in[i];
    const float* f = &v.x;
    unsigned long long ph = 0, pl = 0;
#pragma unroll
    for (int j = 0; j < 4; j++) {
        __nv_bfloat16 hb = __float2bfloat16_rn(f[j]);
        __nv_bfloat16 lb = __float2bfloat16_rn(f[j] - __bfloat162float(hb));
        ph |= (unsigned long long)__bfloat16_as_ushort(hb) << (16 * j);
        pl |= (unsigned long long)__bfloat16_as_ushort(lb) << (16 * j);
    }
    hi[i] = ph; lo[i] = pl;
}

// ---------------- bf16 MMA GEMM (3-product split) ---------------------------
// C[m,n] = sum_k A[m,k]*B[n,k] + bias[n]; A: MxK, B: NxK, both K-contiguous.
constexpr int BM = 128, BN = 128, BK = 64, STAGES = 3;
constexpr int AB_BYTES = BM * BK * 2;          // 16384 per operand half
constexpr int STAGE_BYTES = 4 * AB_BYTES;      // 65536 (Ah,Al,Bh,Bl)
constexpr int GSMEM = STAGES * STAGE_BYTES;    // 196608
constexpr int NT = K_DIM / BK;                 // 16

__global__ void __launch_bounds__(256, 1)
gemm_bf16(const __nv_bfloat16* __restrict__ Ah, const __nv_bfloat16* __restrict__ Al,
          const __nv_bfloat16* __restrict__ Bh, const __nv_bfloat16* __restrict__ Bl,
          const float* __restrict__ bias, float* __restrict__ C)
{
    extern __shared__ char smem[];
    const uint32_t sb = s2u(smem);
    const int tid = threadIdx.x, lane = tid & 31, wid = tid >> 5;
    const int wm = wid >> 2, wn = wid & 3;          // 2 x 4 warp grid
    const int mBase = blockIdx.y * BM, nBase = blockIdx.x * BN;

    // ---- loader mapping: each thread = one row-half (64B) per sub-tile -----
    const int lrow = tid >> 1;                 // 0..127
    const int lc0  = (tid & 1) * 4;            // 16B-chunk base: 0 or 4
    const char* gA[2] = { (const char*)(Ah + (size_t)(mBase + lrow) * K_DIM),
                          (const char*)(Al + (size_t)(mBase + lrow) * K_DIM) };
    const char* gB[2] = { (const char*)(Bh + (size_t)(nBase + lrow) * K_DIM),
                          (const char*)(Bl + (size_t)(nBase + lrow) * K_DIM) };
    const uint32_t swBase = lrow * 128;        // row offset inside a sub-tile

    auto issue = [&](int kt, int s) {
        const uint32_t st = sb + s * STAGE_BYTES;
#pragma unroll
        for (int m = 0; m < 4; m++) {
            const char* g = (m < 2 ? gA[m] : gB[m - 2]) + kt * 128;
            const uint32_t t0 = st + m * AB_BYTES + swBase;
#pragma unroll
            for (int c = 0; c < 4; c++) {
                const int cc = lc0 + c;
                cpasync16(t0 + ((cc ^ (lrow & 7)) << 4), g + cc * 16);
            }
        }
        asm volatile("cp.async.commit_group;");
    };

    float acc[4][4][4];
#pragma unroll
    for (int a = 0; a < 4; a++)
#pragma unroll
        for (int b = 0; b < 4; b++)
#pragma unroll
            for (int c = 0; c < 4; c++) acc[a][b][c] = 0.0f;

    issue(0, 0);
    issue(1, 1);

    const int li = lane >> 3, lj = lane & 7;   // ldmatrix sub-matrix / row

    for (int kt = 0; kt < NT; kt++) {
        asm volatile("cp.async.wait_group %0;" :: "n"(1));
        __syncthreads();
        if (kt + 2 < NT) issue(kt + 2, (kt + 2) % STAGES);
        else asm volatile("cp.async.commit_group;");

        const uint32_t st = sb + (kt % STAGES) * STAGE_BYTES;
        const uint32_t aH = st, aL = st + AB_BYTES;
        const uint32_t bH = st + 2 * AB_BYTES, bL = st + 3 * AB_BYTES;

#pragma unroll
        for (int ks = 0; ks < BK / 16; ks++) {
            uint32_t ah[4][4], al[4][4], bh[2][4], bl[2][4];
#pragma unroll
            for (int mt = 0; mt < 4; mt++) {
                const int r  = wm * 64 + mt * 16 + ((li & 1) << 3) + lj;
                const int c8 = ks * 2 + (li >> 1);
                const uint32_t off = r * 128 + ((c8 ^ (r & 7)) << 4);
                ldsm4(ah[mt], aH + off);
                ldsm4(al[mt], aL + off);
            }
#pragma unroll
            for (int n2 = 0; n2 < 2; n2++) {
                const int r  = wn * 32 + n2 * 16 + ((li >> 1) << 3) + lj;
                const int c8 = ks * 2 + (li & 1);
                const uint32_t off = r * 128 + ((c8 ^ (r & 7)) << 4);
                ldsm4(bh[n2], bH + off);
                ldsm4(bl[n2], bL + off);
            }
#pragma unroll
            for (int mt = 0; mt < 4; mt++)
#pragma unroll
                for (int nt = 0; nt < 4; nt++) {
                    const int n2 = nt >> 1, hh = (nt & 1) * 2;
                    mma_bf16(acc[mt][nt], ah[mt], bh[n2][hh], bh[n2][hh + 1]);
                    mma_bf16(acc[mt][nt], ah[mt], bl[n2][hh], bl[n2][hh + 1]);
                    mma_bf16(acc[mt][nt], al[mt], bh[n2][hh], bh[n2][hh + 1]);
                }
        }
        __syncthreads();
    }

    // ---- epilogue: bias + direct float2 stores ------------------------------
    const int grp = lane >> 2, tq = lane & 3;
#pragma unroll
    for (int nt = 0; nt < 4; nt++) {
        const int col = nBase + wn * 32 + nt * 8 + tq * 2;
        const float2 bv = *(const float2*)&bias[col];
#pragma unroll
        for (int mt = 0; mt < 4; mt++) {
            const int r0 = mBase + wm * 64 + mt * 16 + grp;
            float2 v0 = make_float2(acc[mt][nt][0] + bv.x, acc[mt][nt][1] + bv.y);
            float2 v1 = make_float2(acc[mt][nt][2] + bv.x, acc[mt][nt][3] + bv.y);
            *(float2*)&C[(size_t)r0 * N_ST + col]       = v0;
            *(float2*)&C[(size_t)(r0 + 8) * N_ST + col] = v1;
        }
    }
}

// ---------------- chunked gate + scan ---------------------------------------
// a = sigmoid(-8*softplus(ld)*r) < 0.5 always, so a 64-step warmup
// reconstructs the state to < 2^-64: chunks are fully independent.
constexpr int SC_CH = 64, SC_LEN = 64, SC_WARM = 64;

__device__ __forceinline__ float sigm(float x) { return 1.0f / (1.0f + __expf(-x)); }

__global__ void scan_kernel(const float* __restrict__ h0,
                            const float* __restrict__ ldec,
                            __nv_bfloat16* __restrict__ hs_hi,
                            __nv_bfloat16* __restrict__ hs_lo,
                            float* __restrict__ hlast)
{
    const int n  = blockIdx.x * 128 + threadIdx.x;   // grid.x = 8
    const int b  = blockIdx.y;                       // 4
    const int ch = blockIdx.z;                       // 64
    const float ld = ldec[n];
    const float sp = (ld > 20.0f) ? ld : log1pf(__expf(ld));
    const float c  = -8.0f * sp;
    const size_t base = ((size_t)b * S_DIM) * N_ST + n;

    float h; int s;
    if (ch == 0) { h = h0[b * N_ST + n]; s = 0; }
    else         { h = 0.0f; s = ch * SC_LEN - SC_WARM; }
    const int s1 = ch * SC_LEN, s2 = s1 + SC_LEN;

#pragma unroll 4
    for (; s < s1; ++s) {
        const size_t idx = base + (size_t)s * N_ST;
        const float rv = sigm(g_r[idx]);
        const float iv = sigm(g_i[idx]);
        const float a  = sigm(c * rv);
        const float u  = sqrtf(fmaf(-a, a, 1.000001f)) * iv * g_xp[idx];
        h = fmaf(a, h, u);
    }
#pragma unroll 4
    for (; s < s2; ++s) {
        const size_t idx = base + (size_t)s * N_ST;
        const float rv = sigm(g_r[idx]);
        const float iv = sigm(g_i[idx]);
        const float a  = sigm(c * rv);
        const float u  = sqrtf(fmaf(-a, a, 1.000001f)) * iv * g_xp[idx];
        h = fmaf(a, h, u);
        const __nv_bfloat16 hb = __float2bfloat16_rn(h);
        hs_hi[idx] = hb;
        hs_lo[idx] = __float2bfloat16_rn(h - __bfloat162float(hb));
    }
    if (ch == SC_CH - 1 && hlast) hlast[b * N_ST + n] = h;
}

// ---------------- host launcher ---------------------------------------------
extern "C" void kernel_launch(void* const* d_in, const int* in_sizes, int n_in,
                              void* d_out, int out_size)
{
    const float* x         = (const float*)d_in[0];
    const float* h0        = (const float*)d_in[1];
    const float* W_in      = (const float*)d_in[2];
    const float* b_in      = (const float*)d_in[3];
    const float* W_r       = (const float*)d_in[4];
    const float* b_r       = (const float*)d_in[5];
    const float* W_i       = (const float*)d_in[6];
    const float* b_i       = (const float*)d_in[7];
    const float* log_decay = (const float*)d_in[8];
    const float* W_out     = (const float*)d_in[9];
    const float* b_out     = (const float*)d_in[10];
    float* out = (float*)d_out;

    void *p_xp, *p_r, *p_i, *p_xhi, *p_xlo, *p_hshi, *p_hslo, *p_whi, *p_wlo;
    cudaGetSymbolAddress(&p_xp,   g_xp);
    cudaGetSymbolAddress(&p_r,    g_r);
    cudaGetSymbolAddress(&p_i,    g_i);
    cudaGetSymbolAddress(&p_xhi,  g_xhi);
    cudaGetSymbolAddress(&p_xlo,  g_xlo);
    cudaGetSymbolAddress(&p_hshi, g_hshi);
    cudaGetSymbolAddress(&p_hslo, g_hslo);
    cudaGetSymbolAddress(&p_whi,  g_whi);
    cudaGetSymbolAddress(&p_wlo,  g_wlo);

    cudaFuncSetAttribute(gemm_bf16, cudaFuncAttributeMaxDynamicSharedMemorySize, GSMEM);

    // 1) bf16 hi/lo splits
    split_bf16<<<(M_DIM * K_DIM / 4) / 256, 256>>>(
        (const float4*)x, (unsigned long long*)p_xhi, (unsigned long long*)p_xlo,
        M_DIM * K_DIM / 4);
    const float* Ws[4] = {W_in, W_r, W_i, W_out};
    const size_t WSZ = 1024 * 1024;              // elements per weight matrix
    for (int w = 0; w < 4; w++)
        split_bf16<<<(int)(WSZ / 4) / 256, 256>>>(
            (const float4*)Ws[w],
            (unsigned long long*)p_whi + w * WSZ / 4,
            (unsigned long long*)p_wlo + w * WSZ / 4, (int)(WSZ / 4));

    const __nv_bfloat16* xhi = (const __nv_bfloat16*)p_xhi;
    const __nv_bfloat16* xlo = (const __nv_bfloat16*)p_xlo;
    const __nv_bfloat16* whi = (const __nv_bfloat16*)p_whi;
    const __nv_bfloat16* wlo = (const __nv_bfloat16*)p_wlo;

    dim3 grid(N_ST / BN, M_DIM / BM);            // (8, 128); x-fast -> A L2 reuse

    // 2) input projections
    gemm_bf16<<<grid, 256, GSMEM>>>(xhi, xlo, whi + 0 * WSZ, wlo + 0 * WSZ, b_in, (float*)p_xp);
    gemm_bf16<<<grid, 256, GSMEM>>>(xhi, xlo, whi + 1 * WSZ, wlo + 1 * WSZ, b_r,  (float*)p_r);
    gemm_bf16<<<grid, 256, GSMEM>>>(xhi, xlo, whi + 2 * WSZ, wlo + 2 * WSZ, b_i,  (float*)p_i);

    // 3) gated scan (independent chunks via 64-step warmup)
    const long long need = (long long)M_DIM * D_IN + (long long)B_DIM * N_ST;
    float* hlast = ((long long)out_size >= need) ? out + (size_t)M_DIM * D_IN : nullptr;
    scan_kernel<<<dim3(8, 4, 64), 128>>>(h0, log_decay,
                                         (__nv_bfloat16*)p_hshi, (__nv_bfloat16*)p_hslo,
                                         hlast);

    // 4) output projection
    gemm_bf16<<<grid, 256, GSMEM>>>((const __nv_bfloat16*)p_hshi,
                                    (const __nv_bfloat16*)p_hslo,
                                    whi + 3 * WSZ, wlo + 3 * WSZ, b_out, out);
}

// round 5
// speedup vs baseline: 6.9919x; 1.2932x over previous
#include <cuda_runtime.h>
#include <cuda_bf16.h>
#include <cuda_fp16.h>
#include <math.h>
#include <stdint.h>

// ---------------- problem dims ----------------------------------------------
#define B_DIM 4
#define S_DIM 4096
#define D_IN  1024
#define N_ST  1024
#define M_DIM (B_DIM * S_DIM)      // 16384
#define K_DIM 1024

typedef unsigned long long ull;

// ---------------- static scratch ---------------------------------------------
__device__ float g_xp [(size_t)M_DIM * N_ST];        // x@W_in^T + b_in (fp32)
__device__ float g_ri [(size_t)M_DIM * 2048];        // [r | i] pre-sigmoid (fp32)
__device__ ull   g_xhi[(size_t)M_DIM * K_DIM / 4];   // bf16 hi of x
__device__ ull   g_xlo[(size_t)M_DIM * K_DIM / 4];   // bf16 lo of x
__device__ ull   g_x16[(size_t)M_DIM * K_DIM / 4];   // fp16 of x
__device__ ull   g_hshi[(size_t)M_DIM * N_ST / 4];   // bf16 hi of hs
__device__ ull   g_hslo[(size_t)M_DIM * N_ST / 4];   // bf16 lo of hs
__device__ ull   g_whi [2 * 1024 * 1024 / 4];        // bf16 hi: W_in, W_out
__device__ ull   g_wlo [2 * 1024 * 1024 / 4];        // bf16 lo: W_in, W_out
__device__ ull   g_w16 [2 * 1024 * 1024 / 4];        // fp16:    W_r,  W_i
__device__ float g_bri [2048];                       // concat(b_r, b_i)

// ---------------- asm helpers -------------------------------------------------
__device__ __forceinline__ uint32_t s2u(const void* p) {
    uint32_t a;
    asm("{ .reg .u64 t; cvta.to.shared.u64 t, %1; cvt.u32.u64 %0, t; }"
        : "=r"(a) : "l"(p));
    return a;
}
__device__ __forceinline__ void ldsm4(uint32_t* r, uint32_t a) {
    asm volatile("ldmatrix.sync.aligned.m8n8.x4.shared.b16 {%0,%1,%2,%3},[%4];"
                 : "=r"(r[0]), "=r"(r[1]), "=r"(r[2]), "=r"(r[3]) : "r"(a));
}
__device__ __forceinline__ void mma_bf16(float* d, const uint32_t* a,
                                         uint32_t b0, uint32_t b1) {
    asm volatile("mma.sync.aligned.m16n8k16.row.col.f32.bf16.bf16.f32 "
                 "{%0,%1,%2,%3},{%4,%5,%6,%7},{%8,%9},{%0,%1,%2,%3};"
                 : "+f"(d[0]), "+f"(d[1]), "+f"(d[2]), "+f"(d[3])
                 : "r"(a[0]), "r"(a[1]), "r"(a[2]), "r"(a[3]), "r"(b0), "r"(b1));
}
__device__ __forceinline__ void mma_f16(float* d, const uint32_t* a,
                                        uint32_t b0, uint32_t b1) {
    asm volatile("mma.sync.aligned.m16n8k16.row.col.f32.f16.f16.f32 "
                 "{%0,%1,%2,%3},{%4,%5,%6,%7},{%8,%9},{%0,%1,%2,%3};"
                 : "+f"(d[0]), "+f"(d[1]), "+f"(d[2]), "+f"(d[3])
                 : "r"(a[0]), "r"(a[1]), "r"(a[2]), "r"(a[3]), "r"(b0), "r"(b1));
}
__device__ __forceinline__ void cpasync16(uint32_t s, const void* g) {
    asm volatile("cp.async.cg.shared.global [%0],[%1],16;" :: "r"(s), "l"(g));
}

// ---------------- split kernels -----------------------------------------------
__global__ void split_x3(const float4* __restrict__ in, ull* __restrict__ hi,
                         ull* __restrict__ lo, ull* __restrict__ h16, int n4) {
    int i = blockIdx.x * blockDim.x + threadIdx.x;
    if (i >= n4) return;
    float4 v = in[i];
    const float* f = &v.x;
    ull ph = 0, pl = 0, p16 = 0;
#pragma unroll
    for (int j = 0; j < 4; j++) {
        __nv_bfloat16 hb = __float2bfloat16_rn(f[j]);
        __nv_bfloat16 lb = __float2bfloat16_rn(f[j] - __bfloat162float(hb));
        ph  |= (ull)__bfloat16_as_ushort(hb) << (16 * j);
        pl  |= (ull)__bfloat16_as_ushort(lb) << (16 * j);
        p16 |= (ull)__half_as_ushort(__float2half_rn(f[j])) << (16 * j);
    }
    hi[i] = ph; lo[i] = pl; h16[i] = p16;
}
__global__ void split_bf16(const float4* __restrict__ in, ull* __restrict__ hi,
                           ull* __restrict__ lo, int n4) {
    int i = blockIdx.x * blockDim.x + threadIdx.x;
    if (i >= n4) return;
    float4 v = in[i];
    const float* f = &v.x;
    ull ph = 0, pl = 0;
#pragma unroll
    for (int j = 0; j < 4; j++) {
        __nv_bfloat16 hb = __float2bfloat16_rn(f[j]);
        __nv_bfloat16 lb = __float2bfloat16_rn(f[j] - __bfloat162float(hb));
        ph |= (ull)__bfloat16_as_ushort(hb) << (16 * j);
        pl |= (ull)__bfloat16_as_ushort(lb) << (16 * j);
    }
    hi[i] = ph; lo[i] = pl;
}
__global__ void conv_f16(const float4* __restrict__ in, ull* __restrict__ o, int n4) {
    int i = blockIdx.x * blockDim.x + threadIdx.x;
    if (i >= n4) return;
    float4 v = in[i];
    const float* f = &v.x;
    ull p = 0;
#pragma unroll
    for (int j = 0; j < 4; j++)
        p |= (ull)__half_as_ushort(__float2half_rn(f[j])) << (16 * j);
    o[i] = p;
}
__global__ void concat_bias(const float* __restrict__ a, const float* __restrict__ b,
                            float* __restrict__ dst) {
    int t = blockIdx.x * blockDim.x + threadIdx.x;
    dst[t] = (t < 1024) ? a[t] : b[t - 1024];
}

// ---------------- MMA GEMM (templated product count) --------------------------
// C[m,n] = sum_k A[m,k]*B[n,k] + bias[n]; A: MxK, B: NxK, K-contiguous.
// NPROD==3: bf16, accumulate Ah*Bh + Ah*Bl + Al*Bh.   NPROD==1: fp16, Ah*Bh.
constexpr int BM = 128, BN = 128, BK = 64, STAGES = 3;
constexpr int AB_BYTES = BM * BK * 2;          // 16384 per operand sub-tile
constexpr int NT = K_DIM / BK;                 // 16

template<int NPROD, typename T>
__global__ void __launch_bounds__(256, 1)
gemm_mma(const T* __restrict__ Ah, const T* __restrict__ Al,
         const T* __restrict__ Bh, const T* __restrict__ Bl,
         const float* __restrict__ bias, float* __restrict__ C, int ldc)
{
    constexpr int HALV = (NPROD == 3) ? 2 : 1;
    constexpr int OPS  = 2 * HALV;
    constexpr int STAGE_BYTES = OPS * AB_BYTES;

    extern __shared__ char smem[];
    const uint32_t sb = s2u(smem);
    const int tid = threadIdx.x, lane = tid & 31, wid = tid >> 5;
    const int wm = wid >> 2, wn = wid & 3;          // 2 x 4 warp grid
    const int mBase = blockIdx.y * BM, nBase = blockIdx.x * BN;

    const int lrow = tid >> 1;                 // 0..127
    const int lc0  = (tid & 1) * 4;            // 16B-chunk base: 0 or 4
    const char* gop[OPS];
    gop[0] = (const char*)(Ah + (size_t)(mBase + lrow) * K_DIM);
    if (HALV == 2) gop[1] = (const char*)(Al + (size_t)(mBase + lrow) * K_DIM);
    gop[HALV] = (const char*)(Bh + (size_t)(nBase + lrow) * K_DIM);
    if (HALV == 2) gop[HALV + 1] = (const char*)(Bl + (size_t)(nBase + lrow) * K_DIM);
    const uint32_t swBase = lrow * 128;

    auto issue = [&](int kt, int s) {
        const uint32_t st = sb + s * STAGE_BYTES;
#pragma unroll
        for (int m = 0; m < OPS; m++) {
            const char* g = gop[m] + kt * 128;
            const uint32_t t0 = st + m * AB_BYTES + swBase;
#pragma unroll
            for (int c = 0; c < 4; c++) {
                const int cc = lc0 + c;
                cpasync16(t0 + ((cc ^ (lrow & 7)) << 4), g + cc * 16);
            }
        }
        asm volatile("cp.async.commit_group;");
    };

    float acc[4][4][4];
#pragma unroll
    for (int a = 0; a < 4; a++)
#pragma unroll
        for (int b = 0; b < 4; b++)
#pragma unroll
            for (int c = 0; c < 4; c++) acc[a][b][c] = 0.0f;

    issue(0, 0);
    issue(1, 1);

    const int li = lane >> 3, lj = lane & 7;

    for (int kt = 0; kt < NT; kt++) {
        asm volatile("cp.async.wait_group %0;" :: "n"(1));
        __syncthreads();
        if (kt + 2 < NT) issue(kt + 2, (kt + 2) % STAGES);
        else asm volatile("cp.async.commit_group;");

        const uint32_t st = sb + (kt % STAGES) * STAGE_BYTES;
        const uint32_t aH = st, aL = st + AB_BYTES;
        const uint32_t bH = st + HALV * AB_BYTES, bL = bH + AB_BYTES;

#pragma unroll
        for (int ks = 0; ks < BK / 16; ks++) {
            uint32_t ah[4][4], al[4][4], bh[2][4], bl[2][4];
#pragma unroll
            for (int mt = 0; mt < 4; mt++) {
                const int r  = wm * 64 + mt * 16 + ((li & 1) << 3) + lj;
                const int c8 = ks * 2 + (li >> 1);
                const uint32_t off = r * 128 + ((c8 ^ (r & 7)) << 4);
                ldsm4(ah[mt], aH + off);
                if (HALV == 2) ldsm4(al[mt], aL + off);
            }
#pragma unroll
            for (int n2 = 0; n2 < 2; n2++) {
                const int r  = wn * 32 + n2 * 16 + ((li >> 1) << 3) + lj;
                const int c8 = ks * 2 + (li & 1);
                const uint32_t off = r * 128 + ((c8 ^ (r & 7)) << 4);
                ldsm4(bh[n2], bH + off);
                if (HALV == 2) ldsm4(bl[n2], bL + off);
            }
#pragma unroll
            for (int mt = 0; mt < 4; mt++)
#pragma unroll
                for (int nt = 0; nt < 4; nt++) {
                    const int n2 = nt >> 1, hh = (nt & 1) * 2;
                    if (NPROD == 3) {
                        mma_bf16(acc[mt][nt], ah[mt], bh[n2][hh], bh[n2][hh + 1]);
                        mma_bf16(acc[mt][nt], ah[mt], bl[n2][hh], bl[n2][hh + 1]);
                        mma_bf16(acc[mt][nt], al[mt], bh[n2][hh], bh[n2][hh + 1]);
                    } else {
                        mma_f16(acc[mt][nt], ah[mt], bh[n2][hh], bh[n2][hh + 1]);
                    }
                }
        }
        __syncthreads();
    }

    const int grp = lane >> 2, tq = lane & 3;
#pragma unroll
    for (int nt = 0; nt < 4; nt++) {
        const int col = nBase + wn * 32 + nt * 8 + tq * 2;
        const float2 bv = *(const float2*)&bias[col];
#pragma unroll
        for (int mt = 0; mt < 4; mt++) {
            const int r0 = mBase + wm * 64 + mt * 16 + grp;
            float2 v0 = make_float2(acc[mt][nt][0] + bv.x, acc[mt][nt][1] + bv.y);
            float2 v1 = make_float2(acc[mt][nt][2] + bv.x, acc[mt][nt][3] + bv.y);
            *(float2*)&C[(size_t)r0 * ldc + col]       = v0;
            *(float2*)&C[(size_t)(r0 + 8) * ldc + col] = v1;
        }
    }
}

// ---------------- chunked gate + scan -----------------------------------------
// a = sigmoid(-8*softplus(ld)*r) < 0.5 strictly, so a 32-step warmup
// reconstructs the state to < 2^-32: chunks are fully independent.
constexpr int SC_CH = 32, SC_LEN = 128, SC_WARM = 32;

__device__ __forceinline__ float sigm(float x) { return 1.0f / (1.0f + __expf(-x)); }

__global__ void scan_kernel(const float* __restrict__ h0,
                            const float* __restrict__ ldec,
                            __nv_bfloat16* __restrict__ hs_hi,
                            __nv_bfloat16* __restrict__ hs_lo,
                            float* __restrict__ hlast)
{
    const int n  = blockIdx.x * 128 + threadIdx.x;   // grid.x = 8
    const int b  = blockIdx.y;                       // 4
    const int ch = blockIdx.z;                       // 32
    const float ld = ldec[n];
    const float sp = (ld > 20.0f) ? ld : log1pf(__expf(ld));
    const float c  = -8.0f * sp;
    const size_t base  = ((size_t)b * S_DIM) * N_ST + n;     // xp / hs indexing
    const size_t base2 = ((size_t)b * S_DIM) * 2048 + n;     // r/i indexing

    float h; int s;
    if (ch == 0) { h = h0[b * N_ST + n]; s = 0; }
    else         { h = 0.0f; s = ch * SC_LEN - SC_WARM; }
    const int s1 = ch * SC_LEN, s2 = s1 + SC_LEN;

#pragma unroll 4
    for (; s < s1; ++s) {
        const size_t i2 = base2 + (size_t)s * 2048;
        const float rv = sigm(g_ri[i2]);
        const float iv = sigm(g_ri[i2 + 1024]);
        const float a  = sigm(c * rv);
        const float u  = sqrtf(fmaf(-a, a, 1.000001f)) * iv * g_xp[base + (size_t)s * N_ST];
        h = fmaf(a, h, u);
    }
#pragma unroll 4
    for (; s < s2; ++s) {
        const size_t i2  = base2 + (size_t)s * 2048;
        const size_t idx = base + (size_t)s * N_ST;
        const float rv = sigm(g_ri[i2]);
        const float iv = sigm(g_ri[i2 + 1024]);
        const float a  = sigm(c * rv);
        const float u  = sqrtf(fmaf(-a, a, 1.000001f)) * iv * g_xp[idx];
        h = fmaf(a, h, u);
        const __nv_bfloat16 hb = __float2bfloat16_rn(h);
        hs_hi[idx] = hb;
        hs_lo[idx] = __float2bfloat16_rn(h - __bfloat162float(hb));
    }
    if (ch == SC_CH - 1 && hlast) hlast[b * N_ST + n] = h;
}

// ---------------- host launcher -----------------------------------------------
extern "C" void kernel_launch(void* const* d_in, const int* in_sizes, int n_in,
                              void* d_out, int out_size)
{
    const float* x         = (const float*)d_in[0];
    const float* h0        = (const float*)d_in[1];
    const float* W_in      = (const float*)d_in[2];
    const float* b_in      = (const float*)d_in[3];
    const float* W_r       = (const float*)d_in[4];
    const float* b_r       = (const float*)d_in[5];
    const float* W_i       = (const float*)d_in[6];
    const float* b_i       = (const float*)d_in[7];
    const float* log_decay = (const float*)d_in[8];
    const float* W_out     = (const float*)d_in[9];
    const float* b_out     = (const float*)d_in[10];
    float* out = (float*)d_out;

    void *p_xp, *p_ri, *p_xhi, *p_xlo, *p_x16, *p_hshi, *p_hslo,
         *p_whi, *p_wlo, *p_w16, *p_bri;
    cudaGetSymbolAddress(&p_xp,   g_xp);
    cudaGetSymbolAddress(&p_ri,   g_ri);
    cudaGetSymbolAddress(&p_xhi,  g_xhi);
    cudaGetSymbolAddress(&p_xlo,  g_xlo);
    cudaGetSymbolAddress(&p_x16,  g_x16);
    cudaGetSymbolAddress(&p_hshi, g_hshi);
    cudaGetSymbolAddress(&p_hslo, g_hslo);
    cudaGetSymbolAddress(&p_whi,  g_whi);
    cudaGetSymbolAddress(&p_wlo,  g_wlo);
    cudaGetSymbolAddress(&p_w16,  g_w16);
    cudaGetSymbolAddress(&p_bri,  g_bri);

    constexpr int SM3 = STAGES * 4 * AB_BYTES;   // 196608 (bf16 3-product)
    constexpr int SM1 = STAGES * 2 * AB_BYTES;   //  98304 (fp16 1-product)
    cudaFuncSetAttribute((gemm_mma<3, __nv_bfloat16>),
                         cudaFuncAttributeMaxDynamicSharedMemorySize, SM3);
    cudaFuncSetAttribute((gemm_mma<1, __half>),
                         cudaFuncAttributeMaxDynamicSharedMemorySize, SM1);

    const size_t WSZ = 1024 * 1024;

    // 1) splits / conversions
    split_x3<<<(M_DIM * K_DIM / 4) / 256, 256>>>(
        (const float4*)x, (ull*)p_xhi, (ull*)p_xlo, (ull*)p_x16, M_DIM * K_DIM / 4);
    split_bf16<<<(int)(WSZ / 4) / 256, 256>>>(
        (const float4*)W_in,  (ull*)p_whi,            (ull*)p_wlo,            (int)(WSZ / 4));
    split_bf16<<<(int)(WSZ / 4) / 256, 256>>>(
        (const float4*)W_out, (ull*)p_whi + WSZ / 4,  (ull*)p_wlo + WSZ / 4,  (int)(WSZ / 4));
    conv_f16<<<(int)(WSZ / 4) / 256, 256>>>(
        (const float4*)W_r, (ull*)p_w16,           (int)(WSZ / 4));
    conv_f16<<<(int)(WSZ / 4) / 256, 256>>>(
        (const float4*)W_i, (ull*)p_w16 + WSZ / 4, (int)(WSZ / 4));
    concat_bias<<<2, 1024>>>(b_r, b_i, (float*)p_bri);

    const __nv_bfloat16* xhi = (const __nv_bfloat16*)p_xhi;
    const __nv_bfloat16* xlo = (const __nv_bfloat16*)p_xlo;
    const __nv_bfloat16* whi = (const __nv_bfloat16*)p_whi;
    const __nv_bfloat16* wlo = (const __nv_bfloat16*)p_wlo;

    // 2) x projection (3-product bf16, N=1024)
    gemm_mma<3, __nv_bfloat16><<<dim3(8, 128), 256, SM3>>>(
        xhi, xlo, whi, wlo, b_in, (float*)p_xp, 1024);

    // 3) fused r+i gate projection (1-product fp16, N=2048)
    gemm_mma<1, __half><<<dim3(16, 128), 256, SM1>>>(
        (const __half*)p_x16, (const __half*)nullptr,
        (const __half*)p_w16, (const __half*)nullptr,
        (const float*)p_bri, (float*)p_ri, 2048);

    // 4) gated scan (independent chunks via 32-step warmup)
    const long long need = (long long)M_DIM * D_IN + (long long)B_DIM * N_ST;
    float* hlast = ((long long)out_size >= need) ? out + (size_t)M_DIM * D_IN : nullptr;
    scan_kernel<<<dim3(8, 4, SC_CH), 128>>>(h0, log_decay,
                                            (__nv_bfloat16*)p_hshi,
                                            (__nv_bfloat16*)p_hslo, hlast);

    // 5) output projection (3-product bf16, N=1024)
    gemm_mma<3, __nv_bfloat16><<<dim3(8, 128), 256, SM3>>>(
        (const __nv_bfloat16*)p_hshi, (const __nv_bfloat16*)p_hslo,
        whi + WSZ, wlo + WSZ, b_out, out, 1024);
}

// round 7
// speedup vs baseline: 12.3938x; 1.7726x over previous
#include <cuda_runtime.h>
#include <cuda_fp16.h>
#include <math.h>
#include <stdint.h>

// ---------------- problem dims ----------------------------------------------
#define B_DIM 4
#define S_DIM 4096
#define D_IN  1024
#define N_ST  1024
#define M_DIM (B_DIM * S_DIM)      // 16384
#define K_DIM 1024

typedef unsigned long long ull;

// ---------------- static scratch ---------------------------------------------
__device__ float g_prj [(size_t)M_DIM * 3072];       // [xp | r | i] fp32
__device__ ull   g_x16 [(size_t)M_DIM * K_DIM / 4];  // fp16 x
__device__ ull   g_hs16[(size_t)M_DIM * N_ST / 4];   // fp16 hs
__device__ ull   g_w16 [4 * 1024 * 1024 / 4];        // fp16 W_in,W_r,W_i,W_out
__device__ float g_b3  [3072];                       // concat(b_in, b_r, b_i)

// ---------------- asm helpers -------------------------------------------------
__device__ __forceinline__ uint32_t s2u(const void* p) {
    uint32_t a;
    asm("{ .reg .u64 t; cvta.to.shared.u64 t, %1; cvt.u32.u64 %0, t; }"
        : "=r"(a) : "l"(p));
    return a;
}
__device__ __forceinline__ void ldsm4(uint32_t* r, uint32_t a) {
    asm volatile("ldmatrix.sync.aligned.m8n8.x4.shared.b16 {%0,%1,%2,%3},[%4];"
                 : "=r"(r[0]), "=r"(r[1]), "=r"(r[2]), "=r"(r[3]) : "r"(a));
}
__device__ __forceinline__ void mma_f16(float* d, const uint32_t* a,
                                        uint32_t b0, uint32_t b1) {
    asm volatile("mma.sync.aligned.m16n8k16.row.col.f32.f16.f16.f32 "
                 "{%0,%1,%2,%3},{%4,%5,%6,%7},{%8,%9},{%0,%1,%2,%3};"
                 : "+f"(d[0]), "+f"(d[1]), "+f"(d[2]), "+f"(d[3])
                 : "r"(a[0]), "r"(a[1]), "r"(a[2]), "r"(a[3]), "r"(b0), "r"(b1));
}
__device__ __forceinline__ void cpasync16(uint32_t s, const void* g) {
    asm volatile("cp.async.cg.shared.global [%0],[%1],16;" :: "r"(s), "l"(g));
}

// ---------------- conversion kernels ------------------------------------------
__global__ void conv_f16(const float4* __restrict__ in, ull* __restrict__ o, int n4) {
    int i = blockIdx.x * blockDim.x + threadIdx.x;
    if (i >= n4) return;
    float4 v = in[i];
    const float* f = &v.x;
    ull p = 0;
#pragma unroll
    for (int j = 0; j < 4; j++)
        p |= (ull)__half_as_ushort(__float2half_rn(f[j])) << (16 * j);
    o[i] = p;
}
__global__ void concat_bias3(const float* __restrict__ a, const float* __restrict__ b,
                             const float* __restrict__ c, float* __restrict__ dst) {
    int t = blockIdx.x * blockDim.x + threadIdx.x;   // 3 x 1024
    dst[t] = (t < 1024) ? a[t] : (t < 2048 ? b[t - 1024] : c[t - 2048]);
}

// ---------------- fp16 MMA GEMM (1 product) ----------------------------------
// C[m,n] = sum_k A[m,k]*B[n,k] + bias[n]; A: MxK, B: NxK, K-contiguous.
constexpr int BM = 128, BN = 128, BK = 64, STAGES = 3;
constexpr int AB_BYTES = BM * BK * 2;          // 16384 per operand tile
constexpr int STAGE_BYTES = 2 * AB_BYTES;      // 32768 (A, B)
constexpr int GSMEM = STAGES * STAGE_BYTES;    // 98304 -> 2 CTAs/SM
constexpr int NT = K_DIM / BK;                 // 16

__global__ void __launch_bounds__(256, 2)
gemm_f16(const __half* __restrict__ A, const __half* __restrict__ B,
         const float* __restrict__ bias, float* __restrict__ C, int ldc)
{
    extern __shared__ char smem[];
    const uint32_t sb = s2u(smem);
    const int tid = threadIdx.x, lane = tid & 31, wid = tid >> 5;
    const int wm = wid >> 2, wn = wid & 3;          // 2 x 4 warp grid
    const int mBase = blockIdx.y * BM, nBase = blockIdx.x * BN;

    const int lrow = tid >> 1;                 // 0..127
    const int lc0  = (tid & 1) * 4;            // 16B-chunk base: 0 or 4
    const char* gA = (const char*)(A + (size_t)(mBase + lrow) * K_DIM);
    const char* gB = (const char*)(B + (size_t)(nBase + lrow) * K_DIM);
    const uint32_t swBase = lrow * 128;

    auto issue = [&](int kt, int s) {
        const uint32_t st = sb + s * STAGE_BYTES;
#pragma unroll
        for (int m = 0; m < 2; m++) {
            const char* g = (m == 0 ? gA : gB) + kt * 128;
            const uint32_t t0 = st + m * AB_BYTES + swBase;
#pragma unroll
            for (int c = 0; c < 4; c++) {
                const int cc = lc0 + c;
                cpasync16(t0 + ((cc ^ (lrow & 7)) << 4), g + cc * 16);
            }
        }
        asm volatile("cp.async.commit_group;");
    };

    float acc[4][4][4];
#pragma unroll
    for (int a = 0; a < 4; a++)
#pragma unroll
        for (int b = 0; b < 4; b++)
#pragma unroll
            for (int c = 0; c < 4; c++) acc[a][b][c] = 0.0f;

    issue(0, 0);
    issue(1, 1);

    const int li = lane >> 3, lj = lane & 7;

    for (int kt = 0; kt < NT; kt++) {
        asm volatile("cp.async.wait_group %0;" :: "n"(1));
        __syncthreads();
        if (kt + 2 < NT) issue(kt + 2, (kt + 2) % STAGES);
        else asm volatile("cp.async.commit_group;");

        const uint32_t st = sb + (kt % STAGES) * STAGE_BYTES;
        const uint32_t aS = st, bS = st + AB_BYTES;

#pragma unroll
        for (int ks = 0; ks < BK / 16; ks++) {
            uint32_t ar[4][4], br[2][4];
#pragma unroll
            for (int mt = 0; mt < 4; mt++) {
                const int r  = wm * 64 + mt * 16 + ((li & 1) << 3) + lj;
                const int c8 = ks * 2 + (li >> 1);
                ldsm4(ar[mt], aS + r * 128 + ((c8 ^ (r & 7)) << 4));
            }
#pragma unroll
            for (int n2 = 0; n2 < 2; n2++) {
                const int r  = wn * 32 + n2 * 16 + ((li >> 1) << 3) + lj;
                const int c8 = ks * 2 + (li & 1);
                ldsm4(br[n2], bS + r * 128 + ((c8 ^ (r & 7)) << 4));
            }
#pragma unroll
            for (int mt = 0; mt < 4; mt++)
#pragma unroll
                for (int nt = 0; nt < 4; nt++) {
                    const int n2 = nt >> 1, hh = (nt & 1) * 2;
                    mma_f16(acc[mt][nt], ar[mt], br[n2][hh], br[n2][hh + 1]);
                }
        }
        __syncthreads();
    }

    const int grp = lane >> 2, tq = lane & 3;
#pragma unroll
    for (int nt = 0; nt < 4; nt++) {
        const int col = nBase + wn * 32 + nt * 8 + tq * 2;
        const float2 bv = *(const float2*)&bias[col];
#pragma unroll
        for (int mt = 0; mt < 4; mt++) {
            const int r0 = mBase + wm * 64 + mt * 16 + grp;
            float2 v0 = make_float2(acc[mt][nt][0] + bv.x, acc[mt][nt][1] + bv.y);
            float2 v1 = make_float2(acc[mt][nt][2] + bv.x, acc[mt][nt][3] + bv.y);
            *(float2*)&C[(size_t)r0 * ldc + col]       = v0;
            *(float2*)&C[(size_t)(r0 + 8) * ldc + col] = v1;
        }
    }
}

// ---------------- chunked gate + scan -----------------------------------------
// a = sigmoid(-8*softplus(ld)*r) < 0.5 strictly, so a 32-step warmup
// reconstructs the state to < 2^-32: chunks are fully independent.
constexpr int SC_CH = 32, SC_LEN = 128, SC_WARM = 32;

__device__ __forceinline__ float sigm(float x) { return 1.0f / (1.0f + __expf(-x)); }

__global__ void scan_kernel(const float* __restrict__ h0,
                            const float* __restrict__ ldec,
                            __half* __restrict__ hs16,
                            float* __restrict__ hlast)
{
    const int n  = blockIdx.x * 128 + threadIdx.x;   // grid.x = 8
    const int b  = blockIdx.y;                       // 4
    const int ch = blockIdx.z;                       // 32
    const float ld = ldec[n];
    const float sp = (ld > 20.0f) ? ld : log1pf(__expf(ld));
    const float c  = -8.0f * sp;
    const size_t baseP = ((size_t)b * S_DIM) * 3072 + n;    // g_prj rows
    const size_t baseH = ((size_t)b * S_DIM) * N_ST + n;    // hs rows

    float h; int s;
    if (ch == 0) { h = h0[b * N_ST + n]; s = 0; }
    else         { h = 0.0f; s = ch * SC_LEN - SC_WARM; }
    const int s1 = ch * SC_LEN, s2 = s1 + SC_LEN;

#pragma unroll 4
    for (; s < s1; ++s) {
        const size_t ip = baseP + (size_t)s * 3072;
        const float xv = g_prj[ip];
        const float rv = sigm(g_prj[ip + 1024]);
        const float iv = sigm(g_prj[ip + 2048]);
        const float a  = sigm(c * rv);
        const float u  = sqrtf(fmaf(-a, a, 1.000001f)) * iv * xv;
        h = fmaf(a, h, u);
    }
#pragma unroll 4
    for (; s < s2; ++s) {
        const size_t ip = baseP + (size_t)s * 3072;
        const float xv = g_prj[ip];
        const float rv = sigm(g_prj[ip + 1024]);
        const float iv = sigm(g_prj[ip + 2048]);
        const float a  = sigm(c * rv);
        const float u  = sqrtf(fmaf(-a, a, 1.000001f)) * iv * xv;
        h = fmaf(a, h, u);
        hs16[baseH + (size_t)s * N_ST] = __float2half_rn(h);
    }
    if (ch == SC_CH - 1 && hlast) hlast[b * N_ST + n] = h;
}

// ---------------- host launcher -----------------------------------------------
extern "C" void kernel_launch(void* const* d_in, const int* in_sizes, int n_in,
                              void* d_out, int out_size)
{
    const float* x         = (const float*)d_in[0];
    const float* h0        = (const float*)d_in[1];
    const float* W_in      = (const float*)d_in[2];
    const float* b_in      = (const float*)d_in[3];
    const float* W_r       = (const float*)d_in[4];
    const float* b_r       = (const float*)d_in[5];
    const float* W_i       = (const float*)d_in[6];
    const float* b_i       = (const float*)d_in[7];
    const float* log_decay = (const float*)d_in[8];
    const float* W_out     = (const float*)d_in[9];
    const float* b_out     = (const float*)d_in[10];
    float* out = (float*)d_out;

    void *p_prj, *p_x16, *p_hs16, *p_w16, *p_b3;
    cudaGetSymbolAddress(&p_prj,  g_prj);
    cudaGetSymbolAddress(&p_x16,  g_x16);
    cudaGetSymbolAddress(&p_hs16, g_hs16);
    cudaGetSymbolAddress(&p_w16,  g_w16);
    cudaGetSymbolAddress(&p_b3,   g_b3);

    cudaFuncSetAttribute(gemm_f16, cudaFuncAttributeMaxDynamicSharedMemorySize, GSMEM);

    const size_t WSZ = 1024 * 1024;   // elements per weight matrix
    ull* w16 = (ull*)p_w16;

    // 1) fp16 conversions: x + the 4 weights (W_in|W_r|W_i contiguous for B)
    conv_f16<<<(M_DIM * K_DIM / 4) / 256, 256>>>(
        (const float4*)x, (ull*)p_x16, M_DIM * K_DIM / 4);
    conv_f16<<<(int)(WSZ / 4) / 256, 256>>>((const float4*)W_in,  w16,               (int)(WSZ / 4));
    conv_f16<<<(int)(WSZ / 4) / 256, 256>>>((const float4*)W_r,   w16 + WSZ / 4,     (int)(WSZ / 4));
    conv_f16<<<(int)(WSZ / 4) / 256, 256>>>((const float4*)W_i,   w16 + 2 * WSZ / 4, (int)(WSZ / 4));
    conv_f16<<<(int)(WSZ / 4) / 256, 256>>>((const float4*)W_out, w16 + 3 * WSZ / 4, (int)(WSZ / 4));
    concat_bias3<<<3, 1024>>>(b_in, b_r, b_i, (float*)p_b3);

    // 2) fused projections: [xp | r | i] = x @ [W_in;W_r;W_i]^T  (N = 3072)
    gemm_f16<<<dim3(24, 128), 256, GSMEM>>>(
        (const __half*)p_x16, (const __half*)p_w16,
        (const float*)p_b3, (float*)p_prj, 3072);

    // 3) gated scan (independent chunks via 32-step warmup)
    const long long need = (long long)M_DIM * D_IN + (long long)B_DIM * N_ST;
    float* hlast = ((long long)out_size >= need) ? out + (size_t)M_DIM * D_IN : nullptr;
    scan_kernel<<<dim3(8, 4, SC_CH), 128>>>(h0, log_decay, (__half*)p_hs16, hlast);

    // 4) output projection (N = 1024)
    gemm_f16<<<dim3(8, 128), 256, GSMEM>>>(
        (const __half*)p_hs16, (const __half*)(w16 + 3 * WSZ / 4),
        b_out, out, 1024);
}

// round 11
// speedup vs baseline: 12.8216x; 1.0345x over previous
#include <cuda_runtime.h>
#include <cuda_fp16.h>
#include <math.h>
#include <stdint.h>

// ---------------- problem dims ----------------------------------------------
#define B_DIM 4
#define S_DIM 4096
#define D_IN  1024
#define N_ST  1024
#define M_DIM (B_DIM * S_DIM)      // 16384
#define K_DIM 1024

typedef unsigned long long ull;

// ---------------- static scratch ---------------------------------------------
__device__ __half g_prj [(size_t)M_DIM * 3072];      // [xp | r | i] fp16
__device__ ull    g_x16 [(size_t)M_DIM * K_DIM / 4]; // fp16 x
__device__ ull    g_hs16[(size_t)M_DIM * N_ST / 4];  // fp16 hs
__device__ ull    g_w16 [4 * 1024 * 1024 / 4];       // fp16 W_in,W_r,W_i,W_out
__device__ float  g_b3  [3072];                      // concat(b_in, b_r, b_i)

// ---------------- asm helpers -------------------------------------------------
__device__ __forceinline__ uint32_t s2u(const void* p) {
    uint32_t a;
    asm("{ .reg .u64 t; cvta.to.shared.u64 t, %1; cvt.u32.u64 %0, t; }"
        : "=r"(a) : "l"(p));
    return a;
}
__device__ __forceinline__ void ldsm4(uint32_t* r, uint32_t a) {
    asm volatile("ldmatrix.sync.aligned.m8n8.x4.shared.b16 {%0,%1,%2,%3},[%4];"
                 : "=r"(r[0]), "=r"(r[1]), "=r"(r[2]), "=r"(r[3]) : "r"(a));
}
__device__ __forceinline__ void mma_f16(float* d, const uint32_t* a,
                                        uint32_t b0, uint32_t b1) {
    asm volatile("mma.sync.aligned.m16n8k16.row.col.f32.f16.f16.f32 "
                 "{%0,%1,%2,%3},{%4,%5,%6,%7},{%8,%9},{%0,%1,%2,%3};"
                 : "+f"(d[0]), "+f"(d[1]), "+f"(d[2]), "+f"(d[3])
                 : "r"(a[0]), "r"(a[1]), "r"(a[2]), "r"(a[3]), "r"(b0), "r"(b1));
}
__device__ __forceinline__ void cpasync16(uint32_t s, const void* g) {
    asm volatile("cp.async.cg.shared.global [%0],[%1],16;" :: "r"(s), "l"(g));
}

// ---------------- fused fp16 conversion (x + 4 weights, one launch) ----------
__device__ __forceinline__ ull pack_f16(float4 v) {
    const float* f = &v.x;
    ull p = 0;
#pragma unroll
    for (int j = 0; j < 4; j++)
        p |= (ull)__half_as_ushort(__float2half_rn(f[j])) << (16 * j);
    return p;
}
// x: 4194304 float4s -> dx; weights: 4 x 262144 float4s -> dw (contiguous)
__global__ void conv_all(const float4* __restrict__ x,
                         const float4* __restrict__ w0, const float4* __restrict__ w1,
                         const float4* __restrict__ w2, const float4* __restrict__ w3,
                         ull* __restrict__ dx, ull* __restrict__ dw)
{
    const int gid = blockIdx.x * blockDim.x + threadIdx.x;
    const int NX = M_DIM * K_DIM / 4;          // 4194304
    if (gid < NX) {
        dx[gid] = pack_f16(x[gid]);
    } else {
        const int j = gid - NX;                // 0 .. 4*262144-1
        const int seg = j >> 18, off = j & 0x3FFFF;
        const float4* src = (seg == 0) ? w0 : (seg == 1) ? w1 : (seg == 2) ? w2 : w3;
        dw[j] = pack_f16(src[off]);
    }
}
__global__ void concat_bias3(const float* __restrict__ a, const float* __restrict__ b,
                             const float* __restrict__ c, float* __restrict__ dst) {
    int t = blockIdx.x * blockDim.x + threadIdx.x;   // 3 x 1024
    dst[t] = (t < 1024) ? a[t] : (t < 2048 ? b[t - 1024] : c[t - 2048]);
}

// ---------------- fp16 MMA GEMM ------------------------------------------------
// C[m,n] = sum_k A[m,k]*B[n,k] + bias[n]; A: MxK, B: NxK, K-contiguous.
// OUT16=1 -> fp16 output, OUT16=0 -> fp32 output.
constexpr int BM = 128, BN = 128, BK = 64, STAGES = 3;
constexpr int AB_BYTES = BM * BK * 2;          // 16384 per operand tile
constexpr int STAGE_BYTES = 2 * AB_BYTES;      // 32768 (A, B)
constexpr int GSMEM = STAGES * STAGE_BYTES;    // 98304 -> 2 CTAs/SM
constexpr int NT = K_DIM / BK;                 // 16

template<int OUT16>
__global__ void __launch_bounds__(256, 2)
gemm_f16(const __half* __restrict__ A, const __half* __restrict__ B,
         const float* __restrict__ bias, void* __restrict__ Cv, int ldc)
{
    extern __shared__ char smem[];
    const uint32_t sb = s2u(smem);
    const int tid = threadIdx.x, lane = tid & 31, wid = tid >> 5;
    const int wm = wid >> 2, wn = wid & 3;          // 2 x 4 warp grid
    const int mBase = blockIdx.y * BM, nBase = blockIdx.x * BN;

    const int lrow = tid >> 1;                 // 0..127
    const int lc0  = (tid & 1) * 4;            // 16B-chunk base: 0 or 4
    const char* gA = (const char*)(A + (size_t)(mBase + lrow) * K_DIM);
    const char* gB = (const char*)(B + (size_t)(nBase + lrow) * K_DIM);
    const uint32_t swBase = lrow * 128;

    auto issue = [&](int kt, int s) {
        const uint32_t st = sb + s * STAGE_BYTES;
#pragma unroll
        for (int m = 0; m < 2; m++) {
            const char* g = (m == 0 ? gA : gB) + kt * 128;
            const uint32_t t0 = st + m * AB_BYTES + swBase;
#pragma unroll
            for (int c = 0; c < 4; c++) {
                const int cc = lc0 + c;
                cpasync16(t0 + ((cc ^ (lrow & 7)) << 4), g + cc * 16);
            }
        }
        asm volatile("cp.async.commit_group;");
    };

    float acc[4][4][4];
#pragma unroll
    for (int a = 0; a < 4; a++)
#pragma unroll
        for (int b = 0; b < 4; b++)
#pragma unroll
            for (int c = 0; c < 4; c++) acc[a][b][c] = 0.0f;

    issue(0, 0);
    issue(1, 1);

    const int li = lane >> 3, lj = lane & 7;

    for (int kt = 0; kt < NT; kt++) {
        asm volatile("cp.async.wait_group %0;" :: "n"(1));
        __syncthreads();   // single barrier: joins waits AND fences prev consumption
        if (kt + 2 < NT) issue(kt + 2, (kt + 2) % STAGES);
        else asm volatile("cp.async.commit_group;");

        const uint32_t st = sb + (kt % STAGES) * STAGE_BYTES;
        const uint32_t aS = st, bS = st + AB_BYTES;

#pragma unroll
        for (int ks = 0; ks < BK / 16; ks++) {
            uint32_t ar[4][4], br[2][4];
#pragma unroll
            for (int mt = 0; mt < 4; mt++) {
                const int r  = wm * 64 + mt * 16 + ((li & 1) << 3) + lj;
                const int c8 = ks * 2 + (li >> 1);
                ldsm4(ar[mt], aS + r * 128 + ((c8 ^ (r & 7)) << 4));
            }
#pragma unroll
            for (int n2 = 0; n2 < 2; n2++) {
                const int r  = wn * 32 + n2 * 16 + ((li >> 1) << 3) + lj;
                const int c8 = ks * 2 + (li & 1);
                ldsm4(br[n2], bS + r * 128 + ((c8 ^ (r & 7)) << 4));
            }
#pragma unroll
            for (int mt = 0; mt < 4; mt++)
#pragma unroll
                for (int nt = 0; nt < 4; nt++) {
                    const int n2 = nt >> 1, hh = (nt & 1) * 2;
                    mma_f16(acc[mt][nt], ar[mt], br[n2][hh], br[n2][hh + 1]);
                }
        }
    }

    const int grp = lane >> 2, tq = lane & 3;
#pragma unroll
    for (int nt = 0; nt < 4; nt++) {
        const int col = nBase + wn * 32 + nt * 8 + tq * 2;
        const float2 bv = *(const float2*)&bias[col];
#pragma unroll
        for (int mt = 0; mt < 4; mt++) {
            const int r0 = mBase + wm * 64 + mt * 16 + grp;
            if (OUT16) {
                __half* C = (__half*)Cv;
                __half2 v0 = __floats2half2_rn(acc[mt][nt][0] + bv.x,
                                               acc[mt][nt][1] + bv.y);
                __half2 v1 = __floats2half2_rn(acc[mt][nt][2] + bv.x,
                                               acc[mt][nt][3] + bv.y);
                *(__half2*)&C[(size_t)r0 * ldc + col]       = v0;
                *(__half2*)&C[(size_t)(r0 + 8) * ldc + col] = v1;
            } else {
                float* C = (float*)Cv;
                float2 v0 = make_float2(acc[mt][nt][0] + bv.x, acc[mt][nt][1] + bv.y);
                float2 v1 = make_float2(acc[mt][nt][2] + bv.x, acc[mt][nt][3] + bv.y);
                *(float2*)&C[(size_t)r0 * ldc + col]       = v0;
                *(float2*)&C[(size_t)(r0 + 8) * ldc + col] = v1;
            }
        }
    }
}

// ---------------- chunked gate + scan -----------------------------------------
// a = sigmoid(-8*softplus(ld)*r) < 0.5 strictly, so a 32-step warmup
// reconstructs the state to < 2^-32: chunks are fully independent.
constexpr int SC_CH = 32, SC_LEN = 128, SC_WARM = 32;

__device__ __forceinline__ float sigm(float x) { return 1.0f / (1.0f + __expf(-x)); }

__global__ void scan_kernel(const float* __restrict__ h0,
                            const float* __restrict__ ldec,
                            __half* __restrict__ hs16,
                            float* __restrict__ hlast)
{
    const int n  = blockIdx.x * 128 + threadIdx.x;   // grid.x = 8
    const int b  = blockIdx.y;                       // 4
    const int ch = blockIdx.z;                       // 32
    const float ld = ldec[n];
    const float sp = (ld > 20.0f) ? ld : log1pf(__expf(ld));
    const float c  = -8.0f * sp;
    const size_t baseP = ((size_t)b * S_DIM) * 3072 + n;    // g_prj rows (fp16)
    const size_t baseH = ((size_t)b * S_DIM) * N_ST + n;    // hs rows

    float h; int s;
    if (ch == 0) { h = h0[b * N_ST + n]; s = 0; }
    else         { h = 0.0f; s = ch * SC_LEN - SC_WARM; }
    const int s1 = ch * SC_LEN, s2 = s1 + SC_LEN;

#pragma unroll 4
    for (; s < s1; ++s) {
        const size_t ip = baseP + (size_t)s * 3072;
        const float xv = __half2float(g_prj[ip]);
        const float rv = sigm(__half2float(g_prj[ip + 1024]));
        const float iv = sigm(__half2float(g_prj[ip + 2048]));
        const float a  = sigm(c * rv);
        const float u  = sqrtf(fmaf(-a, a, 1.000001f)) * iv * xv;
        h = fmaf(a, h, u);
    }
#pragma unroll 4
    for (; s < s2; ++s) {
        const size_t ip = baseP + (size_t)s * 3072;
        const float xv = __half2float(g_prj[ip]);
        const float rv = sigm(__half2float(g_prj[ip + 1024]));
        const float iv = sigm(__half2float(g_prj[ip + 2048]));
        const float a  = sigm(c * rv);
        const float u  = sqrtf(fmaf(-a, a, 1.000001f)) * iv * xv;
        h = fmaf(a, h, u);
        hs16[baseH + (size_t)s * N_ST] = __float2half_rn(h);
    }
    if (ch == SC_CH - 1 && hlast) hlast[b * N_ST + n] = h;
}

// ---------------- host launcher -----------------------------------------------
extern "C" void kernel_launch(void* const* d_in, const int* in_sizes, int n_in,
                              void* d_out, int out_size)
{
    const float* x         = (const float*)d_in[0];
    const float* h0        = (const float*)d_in[1];
    const float* W_in      = (const float*)d_in[2];
    const float* b_in      = (const float*)d_in[3];
    const float* W_r       = (const float*)d_in[4];
    const float* b_r       = (const float*)d_in[5];
    const float* W_i       = (const float*)d_in[6];
    const float* b_i       = (const float*)d_in[7];
    const float* log_decay = (const float*)d_in[8];
    const float* W_out     = (const float*)d_in[9];
    const float* b_out     = (const float*)d_in[10];
    float* out = (float*)d_out;

    void *p_prj, *p_x16, *p_hs16, *p_w16, *p_b3;
    cudaGetSymbolAddress(&p_prj,  g_prj);
    cudaGetSymbolAddress(&p_x16,  g_x16);
    cudaGetSymbolAddress(&p_hs16, g_hs16);
    cudaGetSymbolAddress(&p_w16,  g_w16);
    cudaGetSymbolAddress(&p_b3,   g_b3);

    cudaFuncSetAttribute(gemm_f16<1>, cudaFuncAttributeMaxDynamicSharedMemorySize, GSMEM);
    cudaFuncSetAttribute(gemm_f16<0>, cudaFuncAttributeMaxDynamicSharedMemorySize, GSMEM);

    const size_t WSZ = 1024 * 1024;   // elements per weight matrix
    ull* w16 = (ull*)p_w16;

    // 1) single fused fp16 conversion (x + W_in + W_r + W_i + W_out)
    const int TOT4 = M_DIM * K_DIM / 4 + 4 * (int)(WSZ / 4);   // 5242880
    conv_all<<<TOT4 / 256, 256>>>(
        (const float4*)x, (const float4*)W_in, (const float4*)W_r,
        (const float4*)W_i, (const float4*)W_out, (ull*)p_x16, w16);
    concat_bias3<<<3, 1024>>>(b_in, b_r, b_i, (float*)p_b3);

    // 2) fused projections: [xp | r | i] = x @ [W_in;W_r;W_i]^T  (N = 3072, fp16 out)
    gemm_f16<1><<<dim3(24, 128), 256, GSMEM>>>(
        (const __half*)p_x16, (const __half*)p_w16,
        (const float*)p_b3, p_prj, 3072);

    // 3) gated scan (independent chunks via 32-step warmup)
    const long long need = (long long)M_DIM * D_IN + (long long)B_DIM * N_ST;
    float* hlast = ((long long)out_size >= need) ? out + (size_t)M_DIM * D_IN : nullptr;
    scan_kernel<<<dim3(8, 4, SC_CH), 128>>>(h0, log_decay, (__half*)p_hs16, hlast);

    // 4) output projection (N = 1024, fp32 out)
    gemm_f16<0><<<dim3(8, 128), 256, GSMEM>>>(
        (const __half*)p_hs16, (const __half*)(w16 + 3 * WSZ / 4),
        b_out, out, 1024);
}